// round 1
// baseline (speedup 1.0000x reference)
#include <cuda_runtime.h>

// ---------------------------------------------------------------------------
// TContextGGANN_39805756899562
//
// The reference graph has a fixed point at zero: all four hidden states start
// at zeros, every message is elementwise-gated by a hidden state (enc * h),
// and the GRU update (1-z)*h + z*tanh(a@Wox.T + (r*h)@Woh.T) maps (a=0, h=0)
// to exactly 0 for every element. This holds across all LOOPS iterations, and
// the final attention block then sees Q=K=V=0, so A@V = 0 and h_e stays 0.
// The mathematically exact output of the reference is all-zeros for
// (h_e, h_l, h_i, h_m) regardless of inputs.
//
// Hence the optimal kernel is a bandwidth-bound zero-fill of d_out (which the
// harness poisons to 0xAA before timing).
// ---------------------------------------------------------------------------

__global__ void tcg_zero_vec4(float4* __restrict__ out, long long n4) {
    long long i = (long long)blockIdx.x * blockDim.x + threadIdx.x;
    long long stride = (long long)gridDim.x * blockDim.x;
    const float4 z = make_float4(0.0f, 0.0f, 0.0f, 0.0f);
    for (; i < n4; i += stride) {
        out[i] = z;
    }
}

__global__ void tcg_zero_tail(float* __restrict__ out, long long start, long long n) {
    long long i = start + (long long)blockIdx.x * blockDim.x + threadIdx.x;
    if (i < n) {
        out[i] = 0.0f;
    }
}

extern "C" void kernel_launch(void* const* d_in, const int* in_sizes, int n_in,
                              void* d_out, int out_size) {
    (void)d_in; (void)in_sizes; (void)n_in;

    float* out = (float*)d_out;
    long long n  = (long long)out_size;
    long long n4 = n >> 2;           // float4 chunks (d_out is >=256B aligned)
    long long rem_start = n4 << 2;

    if (n4 > 0) {
        const int threads = 256;
        long long want = (n4 + threads - 1) / threads;
        int blocks = (int)(want < 16384 ? want : 16384);
        tcg_zero_vec4<<<blocks, threads>>>((float4*)out, n4);
    }
    if (rem_start < n) {
        long long rem = n - rem_start;
        const int threads = 128;
        int blocks = (int)((rem + threads - 1) / threads);
        tcg_zero_tail<<<blocks, threads>>>(out, rem_start, n);
    }
}

// round 2
// speedup vs baseline: 1.2654x; 1.2654x over previous
#include <cuda_runtime.h>

// ---------------------------------------------------------------------------
// TContextGGANN_39805756899562
//
// Math recap (verified in R1, rel_err = 0.0): the reference network has an
// exact fixed point at zero. All hidden states start at zero; every message
// is gated elementwise by a hidden state; the GRU maps (a=0,h=0) -> 0 bit-
// exactly; the final attention sees Q=K=V=0. Output is identically zero.
//
// So the kernel is a pure zero-fill of d_out (64 MiB fp32). R1's version was
// issue-bound (alu=47%, DRAM=7.4%): grid-stride loop + 64-bit index math per
// single STG.128. This version does 4 statically-unrolled STG.128 per thread
// with int32 indexing, shifting the bottleneck to the store path.
// ---------------------------------------------------------------------------

__global__ void __launch_bounds__(256) tcg_zero4(float4* __restrict__ out, int n4) {
    int t = blockIdx.x * blockDim.x + threadIdx.x;
    int total = gridDim.x * blockDim.x;
    const float4 z = make_float4(0.0f, 0.0f, 0.0f, 0.0f);
    // 4 coalesced STG.128 per thread; fully unrolled, predicated bounds.
    #pragma unroll
    for (int k = 0; k < 4; ++k) {
        int i = t + k * total;
        if (i < n4) out[i] = z;
    }
}

__global__ void tcg_zero_tail(float* __restrict__ out, int start, int n) {
    int i = start + blockIdx.x * blockDim.x + threadIdx.x;
    if (i < n) out[i] = 0.0f;
}

extern "C" void kernel_launch(void* const* d_in, const int* in_sizes, int n_in,
                              void* d_out, int out_size) {
    (void)d_in; (void)in_sizes; (void)n_in;

    float* out = (float*)d_out;
    int n  = out_size;            // 16,777,216 for this problem (fits int32)
    int n4 = n >> 2;              // float4 chunks; d_out is 256B-aligned
    int rem_start = n4 << 2;

    if (n4 > 0) {
        const int threads = 256;
        const int per_thread = 4;
        int blocks = (n4 + threads * per_thread - 1) / (threads * per_thread);
        tcg_zero4<<<blocks, threads>>>((float4*)out, n4);
    }
    if (rem_start < n) {
        int rem = n - rem_start;
        const int threads = 128;
        int blocks = (rem + threads - 1) / threads;
        tcg_zero_tail<<<blocks, threads>>>(out, rem_start, n);
    }
}